// round 14
// baseline (speedup 1.0000x reference)
#include <cuda_runtime.h>
#include <cuda_fp16.h>
#include <cstdint>

// Problem constants (this instance): N=1e6 atoms, D=128, H=64, E=4, M=20000.
#define D_DIM 128
#define H_DIM 64
#define BM 64             // atoms per tile
#define NT 256
#define E_MAX 8
#define PERM_CAP 1250000
#define HIST_BLOCKS 512
#define GRID_PERSIST 592  // 4 CTAs per SM

// dynamic SMEM layout (bytes), per CTA (fp16 tiles, A double buffered):
#define ABUF_STRIDE 16384    // A buf s at s*16384 (16KB each)
#define OFF_B     32768      // B: 128 k x 64 n fp16 = 16KB
#define OFF_SORIG 49152      // ring of 4 x 64 ints (1KB)
#define OFF_B1ALL 50176      // 2KB
#define OFF_W2ALL 52224      // 2KB
#define OFF_ETAG  54272      // ring of 4 ints
#define SMEM_TOTAL 54336     // x4 CTAs = 217.3KB <= 228KB/SM

#define BWORDS 4096          // per-element W1 fp16 image: 4096 u32 (16KB)

__device__ int g_count[E_MAX];
__device__ int g_cursor[E_MAX];
__device__ int g_done;
__device__ int g_perm[PERM_CAP];
__device__ uint32_t g_Wimg[E_MAX * BWORDS];

__device__ __forceinline__ uint32_t cvt_f16x2(float vhi, float vlo) {
    uint32_t r;   // r.lo = fp16(vlo), r.hi = fp16(vhi)
    asm("cvt.rn.f16x2.f32 %0, %1, %2;" : "=r"(r) : "f"(vhi), "f"(vlo));
    return r;
}

// ---------------------------------------------------------------------------
__global__ void k_prep(float* __restrict__ out, const float* __restrict__ W1,
                       int E, int M, int total_slots) {
    int i = blockIdx.x * blockDim.x + threadIdx.x;
    int stride = gridDim.x * blockDim.x;
    for (int j = i; j < M; j += stride) out[j] = 0.0f;
    for (int j = i; j < total_slots; j += stride) g_perm[j] = -1;
    if (i < E_MAX) g_count[i] = 0;
    if (i == E_MAX) g_done = 0;

    for (int it = i; it < E * D_DIM * 16; it += stride) {
        int e = it >> 11;
        int k = (it >> 4) & 127;
        int n4 = it & 15;
        float4 v = *reinterpret_cast<const float4*>(
            W1 + (size_t)e * D_DIM * H_DIM + (size_t)k * H_DIM + n4 * 4);
        uint32_t h01 = cvt_f16x2(v.y, v.x);
        uint32_t h23 = cvt_f16x2(v.w, v.z);
        int w = e * BWORDS + k * 32 + (((n4 >> 1) ^ (k & 7)) << 2) + (n4 & 1) * 2;
        g_Wimg[w]     = h01;
        g_Wimg[w + 1] = h23;
    }
}

__global__ void k_histscan(const int* __restrict__ zidx, int n, int E) {
    __shared__ int sh[E_MAX];
    if (threadIdx.x < E_MAX) sh[threadIdx.x] = 0;
    __syncthreads();
    int i = blockIdx.x * blockDim.x + threadIdx.x;
    int stride = gridDim.x * blockDim.x;
    for (int j = i; j < n; j += stride) atomicAdd(&sh[zidx[j]], 1);
    __syncthreads();
    if (threadIdx.x < E) atomicAdd(&g_count[threadIdx.x], sh[threadIdx.x]);
    __threadfence();
    __syncthreads();
    if (threadIdx.x == 0) {
        int t = atomicAdd(&g_done, 1);
        if (t == gridDim.x - 1) {
            int off = 0;
            for (int e = 0; e < E; e++) {
                g_cursor[e] = off;
                off += ((g_count[e] + BM - 1) / BM) * BM;
            }
        }
    }
}

__global__ void k_scatter(const int* __restrict__ zidx, int n) {
    __shared__ int s_cnt[E_MAX];
    __shared__ int s_off[E_MAX];
    if (threadIdx.x < E_MAX) s_cnt[threadIdx.x] = 0;
    __syncthreads();
    int i = blockIdx.x * blockDim.x + threadIdx.x;
    int e = -1;
    if (i < n) { e = zidx[i]; atomicAdd(&s_cnt[e], 1); }
    __syncthreads();
    if (threadIdx.x < E_MAX && s_cnt[threadIdx.x] > 0)
        s_off[threadIdx.x] = atomicAdd(&g_cursor[threadIdx.x], s_cnt[threadIdx.x]);
    __syncthreads();
    if (threadIdx.x < E_MAX) s_cnt[threadIdx.x] = 0;
    __syncthreads();
    if (i < n) {
        int pos = s_off[e] + atomicAdd(&s_cnt[e], 1);
        g_perm[pos] = i;
    }
}

__device__ __forceinline__ float sspf(float v) {
    return __logf(fmaf(0.5f, __expf(v), 0.5f));
}
__device__ __forceinline__ void mma_f16(float* c, const uint32_t* a,
                                        const uint32_t b0, const uint32_t b1) {
    asm volatile(
        "mma.sync.aligned.m16n8k16.row.col.f32.f16.f16.f32 "
        "{%0,%1,%2,%3}, {%4,%5,%6,%7}, {%8,%9}, {%0,%1,%2,%3};"
        : "+f"(c[0]), "+f"(c[1]), "+f"(c[2]), "+f"(c[3])
        : "r"(a[0]), "r"(a[1]), "r"(a[2]), "r"(a[3]), "r"(b0), "r"(b1));
}
__device__ __forceinline__ void ldsm_x4(uint32_t* r, uint32_t addr) {
    asm volatile("ldmatrix.sync.aligned.m8n8.x4.shared.b16 {%0,%1,%2,%3}, [%4];"
                 : "=r"(r[0]), "=r"(r[1]), "=r"(r[2]), "=r"(r[3]) : "r"(addr));
}
__device__ __forceinline__ void ldsm_x4t(uint32_t* r, uint32_t addr) {
    asm volatile("ldmatrix.sync.aligned.m8n8.x4.trans.shared.b16 {%0,%1,%2,%3}, [%4];"
                 : "=r"(r[0]), "=r"(r[1]), "=r"(r[2]), "=r"(r[3]) : "r"(addr));
}
__device__ __forceinline__ uint32_t smem_u32(const void* p) {
    return (uint32_t)__cvta_generic_to_shared(p);
}

// convert one float4 (4 k-values of one row) to fp16 and store swizzled
__device__ __forceinline__ void store_a(char* abase, float4 v, int row, int lane) {
    uint32_t* AW = reinterpret_cast<uint32_t*>(abase);
    uint32_t h01 = cvt_f16x2(v.y, v.x);
    uint32_t h23 = cvt_f16x2(v.w, v.z);
    int w = row * 64 + ((((lane >> 1) ^ (row & 7)) << 2) + (lane & 1) * 2);
    *reinterpret_cast<uint2*>(&AW[w]) = make_uint2(h01, h23);
}

__device__ __forceinline__ void stage_B(char* smem, int e, int tid) {
    const uint4* gw = reinterpret_cast<const uint4*>(&g_Wimg[e * BWORDS]);
    uint4* sw = reinterpret_cast<uint4*>(smem + OFF_B);
#pragma unroll
    for (int j = 0; j < 4; j++)
        sw[j * NT + tid] = gw[j * NT + tid];
}

// ---------------------------------------------------------------------------
// persistent main kernel (4 CTAs/SM): fp16 single-term MMA, double-buffered A,
// single barrier per tile; ALL gather LDGs issued before MMA and consumed
// after it so loads stay in flight through the compute phase.
// ---------------------------------------------------------------------------
__global__ __launch_bounds__(NT, 4)
void k_main(const float* __restrict__ x, const int* __restrict__ zidx,
            const int* __restrict__ idx_m,
            const float* __restrict__ W1, const float* __restrict__ b1,
            const float* __restrict__ W2, const float* __restrict__ b2,
            float* __restrict__ out, int ntiles) {
    extern __shared__ char smem[];
    int*   sOrig = reinterpret_cast<int*>(smem + OFF_SORIG);   // ring [4][64]
    float* b1all = reinterpret_cast<float*>(smem + OFF_B1ALL);
    float* w2all = reinterpret_cast<float*>(smem + OFF_W2ALL);
    int*   eTag  = reinterpret_cast<int*>(smem + OFF_ETAG);    // ring [4]

    int tid = threadIdx.x;
    int wid = tid >> 5;
    int lane = tid & 31;

    int q = (ntiles + gridDim.x - 1) / gridDim.x;
    int tstart = blockIdx.x * q;
    int tend = min(ntiles, tstart + q);
    if (tstart >= tend) return;
    int L = tend - tstart;

    for (int j = tid; j < E_MAX * H_DIM; j += NT) {
        b1all[j] = b1[j];
        w2all[j] = W2[j];
    }
    if (tid < BM) {
#pragma unroll
        for (int j = 0; j < 2; j++)
            sOrig[j * BM + tid] =
                (j < L) ? g_perm[(size_t)(tstart + j) * BM + tid] : -1;
    }
    if (tid < 2) {
        int o0 = (tid < L) ? g_perm[(size_t)(tstart + tid) * BM] : -1;
        eTag[tid] = (o0 >= 0) ? zidx[o0] : -1;
    }
    __syncthreads();

    int e_cur = eTag[0];
    if (e_cur < 0) return;
    stage_B(smem, e_cur, tid);

    // stage full A(0) into buf0 (8 passes, warp-per-row)
#pragma unroll
    for (int it = 0; it < 8; it++) {
        int row = it * 8 + wid;
        int o = sOrig[row];
        float4 v = make_float4(0.f, 0.f, 0.f, 0.f);
        if (o >= 0)
            v = *reinterpret_cast<const float4*>(x + (size_t)o * D_DIM + lane * 4);
        store_a(smem, v, row, lane);
    }
    // prefetch x(1) rows 0-31
    float4 pref[4];
#pragma unroll
    for (int it = 0; it < 4; it++) {
        int o = sOrig[BM + it * 8 + wid];
        pref[it] = make_float4(0.f, 0.f, 0.f, 0.f);
        if (o >= 0)
            pref[it] = *reinterpret_cast<const float4*>(
                x + (size_t)o * D_DIM + lane * 4);
    }
    __syncthreads();

    // fragment-lane decomposition (8 warps: 2 wm x 4 wn, warp tile 32x16)
    int wm = wid & 1;
    int wn = wid >> 1;
    int g = lane >> 2;
    int tg = lane & 3;
    int lane7 = lane & 7;
    int sub = lane >> 3;
    int subm = sub & 1;
    int subh = sub >> 1;

    uint32_t aBase0 = smem_u32(smem);
    uint32_t bBase = smem_u32(smem + OFF_B);

    int aRow0 = (wm * 32 + subm * 8 + lane7) * 64;
    int aRow1 = aRow0 + 16 * 64;
    int aXor = 4 * lane7;
    int a4h = 4 * subh;
    int bConst = (subm * 8 + lane7) * 32 + ((4 * (wn * 2 + subh)) ^ (4 * lane7));

    for (int l = 0; l < L; l++) {
        int s = l & 1;
        char* abase_nxt = smem + (s ^ 1) * ABUF_STRIDE;
        const int* so = sOrig + (l & 3) * BM;
        bool hasNext = (l + 1 < L);

        // 1. STS pref (rows 0-31 of l+1) into the other buffer
        if (hasNext) {
#pragma unroll
            for (int it = 0; it < 4; it++)
                store_a(abase_nxt, pref[it], it * 8 + wid, lane);
        }
        // 2. issue LDG rows 32-63 of (l+1) — in flight through the MMA
        float4 v[4];
        if (hasNext) {
            const int* sn = sOrig + ((l + 1) & 3) * BM;
#pragma unroll
            for (int it = 0; it < 4; it++) {
                int o = sn[32 + it * 8 + wid];
                v[it] = make_float4(0.f, 0.f, 0.f, 0.f);
                if (o >= 0)
                    v[it] = *reinterpret_cast<const float4*>(
                        x + (size_t)o * D_DIM + lane * 4);
            }
        }
        // 3. issue LDG for perm(l+2)
        int o2 = -1;
        if (tid < BM && l + 2 < L)
            o2 = g_perm[(size_t)(tstart + l + 2) * BM + tid];

        // 4. MMA(l) on current buffer
        uint32_t aBase = aBase0 + s * ABUF_STRIDE;
        float acc[2][2][4];
#pragma unroll
        for (int t2 = 0; t2 < 2; t2++)
#pragma unroll
            for (int u = 0; u < 2; u++)
#pragma unroll
                for (int qq = 0; qq < 4; qq++) acc[t2][u][qq] = 0.0f;

#pragma unroll
        for (int kb = 0; kb < 8; kb++) {
            int aOff = (8 * kb + a4h) ^ aXor;
            uint32_t a0[4], a1[4], bb[4];
            ldsm_x4(a0, aBase + (aRow0 + aOff) * 4);
            ldsm_x4(a1, aBase + (aRow1 + aOff) * 4);
            ldsm_x4t(bb, bBase + (kb * 512 + bConst) * 4);
#pragma unroll
            for (int u = 0; u < 2; u++) {
                mma_f16(acc[0][u], a0, bb[2 * u], bb[2 * u + 1]);
                mma_f16(acc[1][u], a1, bb[2 * u], bb[2 * u + 1]);
            }
        }

        // 5. epilogue(l)
        {
            const float* b1s = b1all + e_cur * H_DIM;
            const float* w2s = w2all + e_cur * H_DIM;
            float b2e = b2[e_cur];
#pragma unroll
            for (int t2 = 0; t2 < 2; t2++) {
                float p0 = 0.0f, p1 = 0.0f;
#pragma unroll
                for (int u = 0; u < 2; u++) {
                    int c0 = wn * 16 + u * 8 + 2 * tg;
                    p0 = fmaf(sspf(acc[t2][u][0] + b1s[c0]),     w2s[c0],     p0);
                    p0 = fmaf(sspf(acc[t2][u][1] + b1s[c0 + 1]), w2s[c0 + 1], p0);
                    p1 = fmaf(sspf(acc[t2][u][2] + b1s[c0]),     w2s[c0],     p1);
                    p1 = fmaf(sspf(acc[t2][u][3] + b1s[c0 + 1]), w2s[c0 + 1], p1);
                }
                p0 += __shfl_xor_sync(0xffffffffu, p0, 1);
                p0 += __shfl_xor_sync(0xffffffffu, p0, 2);
                p1 += __shfl_xor_sync(0xffffffffu, p1, 1);
                p1 += __shfl_xor_sync(0xffffffffu, p1, 2);
                if (tg == 0) {
                    int r0 = wm * 32 + t2 * 16 + g;
                    int o0 = so[r0];
                    int o1 = so[r0 + 8];
                    float bias = (wn == 0) ? b2e : 0.0f;
                    if (o0 >= 0) atomicAdd(&out[idx_m[o0]], p0 + bias);
                    if (o1 >= 0) atomicAdd(&out[idx_m[o1]], p1 + bias);
                }
            }
        }

        // 6. STS v (rows 32-63 of l+1) — loads have landed during MMA
        if (hasNext) {
#pragma unroll
            for (int it = 0; it < 4; it++)
                store_a(abase_nxt, v[it], 32 + it * 8 + wid, lane);
        }
        // 7. commit perm(l+2) + element tag
        if (tid < BM) sOrig[((l + 2) & 3) * BM + tid] = o2;
        if (tid == 0) eTag[(l + 2) & 3] = (o2 >= 0) ? zidx[o2] : -1;

        // 8. element change (rare, uniform condition): guard + restage B
        if (hasNext) {
            int e_next = eTag[(l + 1) & 3];
            if (e_next != e_cur && e_next >= 0) {
                __syncthreads();          // all warps done with old B
                stage_B(smem, e_next, tid);
                e_cur = e_next;
            }
        }

        // 9. single main barrier
        __syncthreads();

        // 10. prefetch x(l+2) rows 0-31 (in flight through next MMA)
        if (l + 2 < L) {
            const int* sn2 = sOrig + ((l + 2) & 3) * BM;
#pragma unroll
            for (int it = 0; it < 4; it++) {
                int o = sn2[it * 8 + wid];
                pref[it] = make_float4(0.f, 0.f, 0.f, 0.f);
                if (o >= 0)
                    pref[it] = *reinterpret_cast<const float4*>(
                        x + (size_t)o * D_DIM + lane * 4);
            }
        }
    }
}

// ---------------------------------------------------------------------------
extern "C" void kernel_launch(void* const* d_in, const int* in_sizes, int n_in,
                              void* d_out, int out_size) {
    const float* x    = (const float*)d_in[0];
    const int*   zidx = (const int*)d_in[1];
    const int*   idxm = (const int*)d_in[2];
    const float* W1   = (const float*)d_in[3];
    const float* b1   = (const float*)d_in[4];
    const float* W2   = (const float*)d_in[5];
    const float* b2   = (const float*)d_in[6];
    float* out = (float*)d_out;

    int N = in_sizes[1];
    int E = in_sizes[6];
    int M = out_size;

    int ntiles = (N + BM - 1) / BM + E;
    int total_slots = ntiles * BM;
    if (total_slots > PERM_CAP) total_slots = PERM_CAP;

    static int smem_set = 0;
    if (!smem_set) {
        cudaFuncSetAttribute(k_main, cudaFuncAttributeMaxDynamicSharedMemorySize,
                             SMEM_TOTAL);
        smem_set = 1;
    }

    k_prep<<<256, 256>>>(out, W1, E, M, total_slots);
    k_histscan<<<HIST_BLOCKS, 256>>>(zidx, N, E);
    k_scatter<<<(N + 255) / 256, 256>>>(zidx, N);
    k_main<<<GRID_PERSIST, NT, SMEM_TOTAL>>>(x, zidx, idxm, W1, b1, W2, b2,
                                             out, ntiles);
}

// round 15
// speedup vs baseline: 1.1686x; 1.1686x over previous
#include <cuda_runtime.h>
#include <cuda_fp16.h>
#include <cstdint>

// Problem constants (this instance): N=1e6 atoms, D=128, H=64, E=4, M=20000.
#define D_DIM 128
#define H_DIM 64
#define BM 64             // atoms per tile
#define NT 256
#define E_MAX 8
#define PERM_CAP 1250000
#define HIST_BLOCKS 512
#define GRID_PERSIST 592  // 4 CTAs per SM (occupancy cap: 32 warps)

// dynamic SMEM layout (bytes), per CTA (fp16 single-term tiles):
#define OFF_A     0          // A: 64 rows x 128 k fp16 = 16KB
#define OFF_B     16384      // B: 128 k x 64 n fp16 = 16KB
#define OFF_SORIG 32768      // ring of 4 x 64 ints (1KB)
#define OFF_B1ALL 33792      // 2KB
#define OFF_W2ALL 35840      // 2KB
#define OFF_ETAG  37888      // ring of 4 ints
#define SMEM_TOTAL 38144     // x4 CTAs = 152.6KB <= 228KB/SM

#define BWORDS 4096          // per-element W1 fp16 image: 4096 u32 (16KB)

__device__ int g_count[E_MAX];
__device__ int g_cursor[E_MAX];
__device__ int g_done;
__device__ int g_perm[PERM_CAP];
__device__ uint32_t g_Wimg[E_MAX * BWORDS];

__device__ __forceinline__ uint32_t cvt_f16x2(float vhi, float vlo) {
    uint32_t r;   // r.lo = fp16(vlo), r.hi = fp16(vhi)
    asm("cvt.rn.f16x2.f32 %0, %1, %2;" : "=r"(r) : "f"(vhi), "f"(vlo));
    return r;
}

// ---------------------------------------------------------------------------
__global__ void k_prep(float* __restrict__ out, const float* __restrict__ W1,
                       int E, int M, int total_slots) {
    int i = blockIdx.x * blockDim.x + threadIdx.x;
    int stride = gridDim.x * blockDim.x;
    for (int j = i; j < M; j += stride) out[j] = 0.0f;
    for (int j = i; j < total_slots; j += stride) g_perm[j] = -1;
    if (i < E_MAX) g_count[i] = 0;
    if (i == E_MAX) g_done = 0;

    for (int it = i; it < E * D_DIM * 16; it += stride) {
        int e = it >> 11;
        int k = (it >> 4) & 127;
        int n4 = it & 15;
        float4 v = *reinterpret_cast<const float4*>(
            W1 + (size_t)e * D_DIM * H_DIM + (size_t)k * H_DIM + n4 * 4);
        uint32_t h01 = cvt_f16x2(v.y, v.x);
        uint32_t h23 = cvt_f16x2(v.w, v.z);
        int w = e * BWORDS + k * 32 + (((n4 >> 1) ^ (k & 7)) << 2) + (n4 & 1) * 2;
        g_Wimg[w]     = h01;
        g_Wimg[w + 1] = h23;
    }
}

__global__ void k_histscan(const int* __restrict__ zidx, int n, int E) {
    __shared__ int sh[E_MAX];
    if (threadIdx.x < E_MAX) sh[threadIdx.x] = 0;
    __syncthreads();
    int i = blockIdx.x * blockDim.x + threadIdx.x;
    int stride = gridDim.x * blockDim.x;
    for (int j = i; j < n; j += stride) atomicAdd(&sh[zidx[j]], 1);
    __syncthreads();
    if (threadIdx.x < E) atomicAdd(&g_count[threadIdx.x], sh[threadIdx.x]);
    __threadfence();
    __syncthreads();
    if (threadIdx.x == 0) {
        int t = atomicAdd(&g_done, 1);
        if (t == gridDim.x - 1) {
            int off = 0;
            for (int e = 0; e < E; e++) {
                g_cursor[e] = off;
                off += ((g_count[e] + BM - 1) / BM) * BM;
            }
        }
    }
}

__global__ void k_scatter(const int* __restrict__ zidx, int n) {
    __shared__ int s_cnt[E_MAX];
    __shared__ int s_off[E_MAX];
    if (threadIdx.x < E_MAX) s_cnt[threadIdx.x] = 0;
    __syncthreads();
    int i = blockIdx.x * blockDim.x + threadIdx.x;
    int e = -1;
    if (i < n) { e = zidx[i]; atomicAdd(&s_cnt[e], 1); }
    __syncthreads();
    if (threadIdx.x < E_MAX && s_cnt[threadIdx.x] > 0)
        s_off[threadIdx.x] = atomicAdd(&g_cursor[threadIdx.x], s_cnt[threadIdx.x]);
    __syncthreads();
    if (threadIdx.x < E_MAX) s_cnt[threadIdx.x] = 0;
    __syncthreads();
    if (i < n) {
        int pos = s_off[e] + atomicAdd(&s_cnt[e], 1);
        g_perm[pos] = i;
    }
}

__device__ __forceinline__ float sspf(float v) {
    return __logf(fmaf(0.5f, __expf(v), 0.5f));
}
__device__ __forceinline__ void mma_f16(float* c, const uint32_t* a,
                                        const uint32_t b0, const uint32_t b1) {
    asm volatile(
        "mma.sync.aligned.m16n8k16.row.col.f32.f16.f16.f32 "
        "{%0,%1,%2,%3}, {%4,%5,%6,%7}, {%8,%9}, {%0,%1,%2,%3};"
        : "+f"(c[0]), "+f"(c[1]), "+f"(c[2]), "+f"(c[3])
        : "r"(a[0]), "r"(a[1]), "r"(a[2]), "r"(a[3]), "r"(b0), "r"(b1));
}
__device__ __forceinline__ void ldsm_x4(uint32_t* r, uint32_t addr) {
    asm volatile("ldmatrix.sync.aligned.m8n8.x4.shared.b16 {%0,%1,%2,%3}, [%4];"
                 : "=r"(r[0]), "=r"(r[1]), "=r"(r[2]), "=r"(r[3]) : "r"(addr));
}
__device__ __forceinline__ void ldsm_x4t(uint32_t* r, uint32_t addr) {
    asm volatile("ldmatrix.sync.aligned.m8n8.x4.trans.shared.b16 {%0,%1,%2,%3}, [%4];"
                 : "=r"(r[0]), "=r"(r[1]), "=r"(r[2]), "=r"(r[3]) : "r"(addr));
}
__device__ __forceinline__ uint32_t smem_u32(const void* p) {
    return (uint32_t)__cvta_generic_to_shared(p);
}

// convert one float4 (4 k-values of one row) to fp16 and store swizzled
__device__ __forceinline__ void store_a(char* smem, float4 v, int row, int lane) {
    uint32_t* AW = reinterpret_cast<uint32_t*>(smem + OFF_A);
    uint32_t h01 = cvt_f16x2(v.y, v.x);
    uint32_t h23 = cvt_f16x2(v.w, v.z);
    int w = row * 64 + ((((lane >> 1) ^ (row & 7)) << 2) + (lane & 1) * 2);
    *reinterpret_cast<uint2*>(&AW[w]) = make_uint2(h01, h23);
}

__device__ __forceinline__ void stage_B(char* smem, int e, int tid) {
    const uint4* gw = reinterpret_cast<const uint4*>(&g_Wimg[e * BWORDS]);
    uint4* sw = reinterpret_cast<uint4*>(smem + OFF_B);
#pragma unroll
    for (int j = 0; j < 4; j++)
        sw[j * NT + tid] = gw[j * NT + tid];
}

// ---------------------------------------------------------------------------
// persistent main kernel (4 CTAs/SM): single fp16 MMA term, single A buffer,
// two barriers/tile, half-register prefetch + JIT gather. JIT-gather LDGs are
// issued FIRST in the staging phase so the pref-STS/convert work and perm LDG
// run under their latency; v is dead before the MMA phase (one live prefetch
// window only — the R14 lesson).
// ---------------------------------------------------------------------------
__global__ __launch_bounds__(NT, 4)
void k_main(const float* __restrict__ x, const int* __restrict__ zidx,
            const int* __restrict__ idx_m,
            const float* __restrict__ W1, const float* __restrict__ b1,
            const float* __restrict__ W2, const float* __restrict__ b2,
            float* __restrict__ out, int ntiles) {
    extern __shared__ char smem[];
    int*   sOrig = reinterpret_cast<int*>(smem + OFF_SORIG);   // ring [4][64]
    float* b1all = reinterpret_cast<float*>(smem + OFF_B1ALL);
    float* w2all = reinterpret_cast<float*>(smem + OFF_W2ALL);
    int*   eTag  = reinterpret_cast<int*>(smem + OFF_ETAG);    // ring [4]

    int tid = threadIdx.x;
    int wid = tid >> 5;
    int lane = tid & 31;

    int q = (ntiles + gridDim.x - 1) / gridDim.x;
    int tstart = blockIdx.x * q;
    int tend = min(ntiles, tstart + q);
    if (tstart >= tend) return;
    int L = tend - tstart;

    for (int j = tid; j < E_MAX * H_DIM; j += NT) {
        b1all[j] = b1[j];
        w2all[j] = W2[j];
    }
    if (tid < BM) {
#pragma unroll
        for (int j = 0; j < 2; j++)
            sOrig[j * BM + tid] =
                (j < L) ? g_perm[(size_t)(tstart + j) * BM + tid] : -1;
    }
    if (tid < 2) {
        int o0 = (tid < L) ? g_perm[(size_t)(tstart + tid) * BM] : -1;
        eTag[tid] = (o0 >= 0) ? zidx[o0] : -1;
    }
    __syncthreads();

    int e_cur = eTag[0];
    if (e_cur < 0) return;
    stage_B(smem, e_cur, tid);

    // prefetch x(0) rows 0-31 (rows 32-63 gathered JIT in the loop)
    float4 pref[4];
#pragma unroll
    for (int it = 0; it < 4; it++) {
        int o = sOrig[it * 8 + wid];
        pref[it] = make_float4(0.f, 0.f, 0.f, 0.f);
        if (o >= 0)
            pref[it] = *reinterpret_cast<const float4*>(
                x + (size_t)o * D_DIM + lane * 4);
    }

    // fragment-lane decomposition (8 warps: 2 wm x 4 wn, warp tile 32x16)
    int wm = wid & 1;
    int wn = wid >> 1;
    int g = lane >> 2;
    int tg = lane & 3;
    int lane7 = lane & 7;
    int sub = lane >> 3;
    int subm = sub & 1;
    int subh = sub >> 1;

    uint32_t aBase = smem_u32(smem + OFF_A);
    uint32_t bBase = smem_u32(smem + OFF_B);

    int aRow0 = (wm * 32 + subm * 8 + lane7) * 64;
    int aRow1 = aRow0 + 16 * 64;
    int aXor = 4 * lane7;
    int a4h = 4 * subh;
    int bConst = (subm * 8 + lane7) * 32 + ((4 * (wn * 2 + subh)) ^ (4 * lane7));

    for (int l = 0; l < L; l++) {
        const int* so = sOrig + (l & 3) * BM;

        // 1. issue JIT-gather LDGs for rows 32-63 FIRST (longest latency)
        float4 v[4];
#pragma unroll
        for (int it = 0; it < 4; it++) {
            int o = so[32 + it * 8 + wid];
            v[it] = make_float4(0.f, 0.f, 0.f, 0.f);
            if (o >= 0)
                v[it] = *reinterpret_cast<const float4*>(
                    x + (size_t)o * D_DIM + lane * 4);
        }
        // 2. issue LDG for perm(l+2) under the same shadow
        int o2 = -1;
        if (tid < BM && l + 2 < L)
            o2 = g_perm[(size_t)(tstart + l + 2) * BM + tid];

        // 3. STS A(l) rows 0-31 from pref (convert work hides LDG latency)
#pragma unroll
        for (int it = 0; it < 4; it++)
            store_a(smem, pref[it], it * 8 + wid, lane);

        // 4. STS rows 32-63 (v dead after this — before the MMA phase)
#pragma unroll
        for (int it = 0; it < 4; it++)
            store_a(smem, v[it], 32 + it * 8 + wid, lane);

        __syncthreads();   // barrier1: A (and B after change) visible

        // 5. prefetch x(l+1) rows 0-31 (LDG latency hides under MMA)
        if (l + 1 < L) {
            const int* sn = sOrig + ((l + 1) & 3) * BM;
#pragma unroll
            for (int it = 0; it < 4; it++) {
                int o = sn[it * 8 + wid];
                pref[it] = make_float4(0.f, 0.f, 0.f, 0.f);
                if (o >= 0)
                    pref[it] = *reinterpret_cast<const float4*>(
                        x + (size_t)o * D_DIM + lane * 4);
            }
        }

        // 6. MMA(l): single fp16 term
        float acc[2][2][4];
#pragma unroll
        for (int t2 = 0; t2 < 2; t2++)
#pragma unroll
            for (int u = 0; u < 2; u++)
#pragma unroll
                for (int qq = 0; qq < 4; qq++) acc[t2][u][qq] = 0.0f;

#pragma unroll
        for (int kb = 0; kb < 8; kb++) {
            int aOff = (8 * kb + a4h) ^ aXor;
            uint32_t a0[4], a1[4], bb[4];
            ldsm_x4(a0, aBase + (aRow0 + aOff) * 4);
            ldsm_x4(a1, aBase + (aRow1 + aOff) * 4);
            ldsm_x4t(bb, bBase + (kb * 512 + bConst) * 4);
#pragma unroll
            for (int u = 0; u < 2; u++) {
                mma_f16(acc[0][u], a0, bb[2 * u], bb[2 * u + 1]);
                mma_f16(acc[1][u], a1, bb[2 * u], bb[2 * u + 1]);
            }
        }

        // 7. epilogue(l)
        {
            const float* b1s = b1all + e_cur * H_DIM;
            const float* w2s = w2all + e_cur * H_DIM;
            float b2e = b2[e_cur];
#pragma unroll
            for (int t2 = 0; t2 < 2; t2++) {
                float p0 = 0.0f, p1 = 0.0f;
#pragma unroll
                for (int u = 0; u < 2; u++) {
                    int c0 = wn * 16 + u * 8 + 2 * tg;
                    p0 = fmaf(sspf(acc[t2][u][0] + b1s[c0]),     w2s[c0],     p0);
                    p0 = fmaf(sspf(acc[t2][u][1] + b1s[c0 + 1]), w2s[c0 + 1], p0);
                    p1 = fmaf(sspf(acc[t2][u][2] + b1s[c0]),     w2s[c0],     p1);
                    p1 = fmaf(sspf(acc[t2][u][3] + b1s[c0 + 1]), w2s[c0 + 1], p1);
                }
                p0 += __shfl_xor_sync(0xffffffffu, p0, 1);
                p0 += __shfl_xor_sync(0xffffffffu, p0, 2);
                p1 += __shfl_xor_sync(0xffffffffu, p1, 1);
                p1 += __shfl_xor_sync(0xffffffffu, p1, 2);
                if (tg == 0) {
                    int r0 = wm * 32 + t2 * 16 + g;
                    int o0 = so[r0];
                    int o1 = so[r0 + 8];
                    float bias = (wn == 0) ? b2e : 0.0f;
                    if (o0 >= 0) atomicAdd(&out[idx_m[o0]], p0 + bias);
                    if (o1 >= 0) atomicAdd(&out[idx_m[o1]], p1 + bias);
                }
            }
        }

        // 8. commit perm(l+2) + element tag
        if (tid < BM) sOrig[((l + 2) & 3) * BM + tid] = o2;
        if (tid == 0) eTag[(l + 2) & 3] = (o2 >= 0) ? zidx[o2] : -1;

        __syncthreads();   // barrier2: MMA reads done, ring committed

        // 9. element change (rare): restage B (visible by next barrier1)
        if (l + 1 < L) {
            int e_next = eTag[(l + 1) & 3];
            if (e_next != e_cur && e_next >= 0) {
                stage_B(smem, e_next, tid);
            }
            if (e_next >= 0) e_cur = e_next;
        }
    }
}

// ---------------------------------------------------------------------------
extern "C" void kernel_launch(void* const* d_in, const int* in_sizes, int n_in,
                              void* d_out, int out_size) {
    const float* x    = (const float*)d_in[0];
    const int*   zidx = (const int*)d_in[1];
    const int*   idxm = (const int*)d_in[2];
    const float* W1   = (const float*)d_in[3];
    const float* b1   = (const float*)d_in[4];
    const float* W2   = (const float*)d_in[5];
    const float* b2   = (const float*)d_in[6];
    float* out = (float*)d_out;

    int N = in_sizes[1];
    int E = in_sizes[6];
    int M = out_size;

    int ntiles = (N + BM - 1) / BM + E;
    int total_slots = ntiles * BM;
    if (total_slots > PERM_CAP) total_slots = PERM_CAP;

    static int smem_set = 0;
    if (!smem_set) {
        cudaFuncSetAttribute(k_main, cudaFuncAttributeMaxDynamicSharedMemorySize,
                             SMEM_TOTAL);
        smem_set = 1;
    }

    k_prep<<<256, 256>>>(out, W1, E, M, total_slots);
    k_histscan<<<HIST_BLOCKS, 256>>>(zidx, N, E);
    k_scatter<<<(N + 255) / 256, 256>>>(zidx, N);
    k_main<<<GRID_PERSIST, NT, SMEM_TOTAL>>>(x, zidx, idxm, W1, b1, W2, b2,
                                             out, ntiles);
}